// round 16
// baseline (speedup 1.0000x reference)
#include <cuda_runtime.h>
#include <cstdint>

// LanczosInterpolationLayer: x f32 [32,3,512,512] -> Lanczos4 2x upsample ->
// per-image range renormalize -> *255 -> uint8 (saturating trunc) -> f32 out.
//
// R14 (131.3us) = sampled doNorm decision + early-exit exact pass + pass-2.
// R15 shrinks decision overhead:
//  - k_sample: one block per IMAGE (grid 32; 16x16 samples/ch at stride 64,
//    3 channels/thread), reduces in-block, writes ONE float g_srange[img].
//  - both passes: prologue = single broadcast load of g_srange (no per-block
//    12-wide reduce); pass-2 skips the 384-partial reduce when decided.
//  - exact fallback path retained verbatim (correct for ANY input).

#define NIMG   32
#define NCH    96
#define IN_SZ  512
#define OUT_SZ 1024
#define TILE_W 64           // output cols per block
#define TILE_H 128          // output rows per block
#define PAT_W  40           // input patch cols (32 + 8 halo)
#define PAT_H  72           // input patch rows (64 + 8 halo)
#define PSTR   41           // s_in stride (odd -> conflict-free)
#define USTR   41           // s_ut stride [orow][icol] (conflict-free)
#define SLOTS  128          // blocks per channel (16 x * 8 y)

__device__ float g_pmin[NCH * SLOTS];
__device__ float g_pmax[NCH * SLOTS];
__device__ float g_srange[NIMG];      // sampled range per image (no init)

// Normalized Lanczos4 weights, even phase (output 2m): tap j hits input m-4+j.
#define WE0 (-0.0039706f)
#define WE1 ( 0.0314676f)
#define WE2 (-0.0916620f)
#define WE3 ( 0.2826868f)
#define WE4 ( 0.8933939f)
#define WE5 (-0.1523043f)
#define WE6 ( 0.0554435f)
#define WE7 (-0.0150549f)

#define EVEN8(a0,a1,a2,a3,a4,a5,a6,a7) \
  fmaf((a7), WE7, fmaf((a6), WE6, fmaf((a5), WE5, fmaf((a4), WE4, \
  fmaf((a3), WE3, fmaf((a2), WE2, fmaf((a1), WE1, (a0) * WE0)))))))
#define ODD8(a1,a2,a3,a4,a5,a6,a7,a8) \
  fmaf((a8), WE0, fmaf((a7), WE1, fmaf((a6), WE2, fmaf((a5), WE3, \
  fmaf((a4), WE4, fmaf((a3), WE5, fmaf((a2), WE6, (a1) * WE7)))))))

// ---- sampled decision: 16x16 exact resized values per channel, 1 blk/img ----
__global__ void __launch_bounds__(256)
k_sample(const float* __restrict__ x)
{
    __shared__ float sm[16];
    const int tid = threadIdx.x;
    const int img = blockIdx.x;
    const int rp  = tid >> 4;            // 0..15
    const int cp  = tid & 15;            // 0..15
    const int m   = rp << 5;             // input row base (output row 64r')
    const int n   = cp << 5;             // input col base (output col 64c')

    float vmin = __int_as_float(0x7f800000);
    float vmax = -vmin;

    #pragma unroll
    for (int ch = 0; ch < 3; ch++) {
        const float* src = x + (size_t)(img * 3 + ch) * (IN_SZ * IN_SZ);
        float rv[8];
        #pragma unroll
        for (int i = 0; i < 8; i++) {
            int gy = min(max(m - 4 + i, 0), IN_SZ - 1);
            const float* row = src + gy * IN_SZ;
            float a0, a1, a2, a3, a4, a5, a6, a7;
            if (cp == 0) {                // cols -4..3 clamp to 0
                a0 = a1 = a2 = a3 = a4 = row[0];
                a5 = row[1]; a6 = row[2]; a7 = row[3];
            } else {                      // cols n-4..n+3, 16B aligned
                const float4* rr = reinterpret_cast<const float4*>(row + n - 4);
                float4 A = rr[0], B = rr[1];
                a0 = A.x; a1 = A.y; a2 = A.z; a3 = A.w;
                a4 = B.x; a5 = B.y; a6 = B.z; a7 = B.w;
            }
            rv[i] = EVEN8(a0, a1, a2, a3, a4, a5, a6, a7);
        }
        float v = EVEN8(rv[0], rv[1], rv[2], rv[3], rv[4], rv[5], rv[6], rv[7]);
        vmin = fminf(vmin, v);
        vmax = fmaxf(vmax, v);
    }

    #pragma unroll
    for (int s = 16; s; s >>= 1) {
        vmin = fminf(vmin, __shfl_xor_sync(0xffffffffu, vmin, s));
        vmax = fmaxf(vmax, __shfl_xor_sync(0xffffffffu, vmax, s));
    }
    if ((tid & 31) == 0) { sm[tid >> 5] = vmin; sm[8 + (tid >> 5)] = vmax; }
    __syncthreads();
    if (tid == 0) {
        float mn = sm[0], mx = sm[8];
        #pragma unroll
        for (int i = 1; i < 8; i++) {
            mn = fminf(mn, sm[i]);
            mx = fmaxf(mx, sm[8 + i]);
        }
        g_srange[img] = mx - mn;
    }
}

template <bool WRITE>
__global__ void __launch_bounds__(256, 5)
k_resize(const float* __restrict__ x, float* __restrict__ out)
{
    __shared__ float s_in[PAT_H * PSTR];    // input patch  [irow][icol]
    __shared__ float s_ut[TILE_H * USTR];   // H-resampled  [orow][icol]
    __shared__ float s_red[16];
    __shared__ float s_srange;

    const int tid = threadIdx.x;
    const int bc  = blockIdx.z;                  // image*3 + channel
    const int m0  = blockIdx.y * (TILE_H / 2);   // input row base
    const int n0  = blockIdx.x * (TILE_W / 2);   // input col base
    const int img = bc / 3;
    const float* src = x + (size_t)bc * (IN_SZ * IN_SZ);

    // ---- prologue: one broadcast load of the sampled range ----
    if (tid == 0) s_srange = g_srange[img];
    __syncthreads();
    const bool decided = s_srange > 1.001f;

    if (!WRITE && decided) return;      // doNorm certain; skip exact pass

    // ---- pass 2, undecided only: reduce 384 exact min/max partials ----
    if (WRITE && !decided) {
        const int img3 = img * 3;
        float a = __int_as_float(0x7f800000);
        float b = -a;
        #pragma unroll
        for (int i = 0; i < 2; i++) {
            int idx = tid + 256 * i;
            if (idx < 3 * SLOTS) {
                a = fminf(a, g_pmin[img3 * SLOTS + idx]);
                b = fmaxf(b, g_pmax[img3 * SLOTS + idx]);
            }
        }
        #pragma unroll
        for (int m = 16; m; m >>= 1) {
            a = fminf(a, __shfl_xor_sync(0xffffffffu, a, m));
            b = fmaxf(b, __shfl_xor_sync(0xffffffffu, b, m));
        }
        if ((tid & 31) == 0) {
            s_red[tid >> 5]       = a;
            s_red[8 + (tid >> 5)] = b;
        }
    }

    // ---- stage A: load input patch with replicate border ----
    #pragma unroll
    for (int i = 0; i < 12; i++) {
        int idx = tid + 256 * i;
        if (idx < PAT_H * PAT_W) {
            int r = idx / PAT_W;
            int c = idx - r * PAT_W;
            int gy = min(max(m0 - 4 + r, 0), IN_SZ - 1);
            int gx = min(max(n0 - 4 + c, 0), IN_SZ - 1);
            s_in[r * PSTR + c] = src[gy * IN_SZ + gx];
        }
    }
    __syncthreads();

    // epilogue constant: f = clamp(trunc(min(P1*v, 255)), 0, 255)
    float P1 = 255.0f;
    if (WRITE) {
        bool doNorm = true;
        if (!decided) {
            float mn = s_red[0], mx = s_red[8];
            #pragma unroll
            for (int i = 1; i < 8; i++) {
                mn = fminf(mn, s_red[i]);
                mx = fmaxf(mx, s_red[8 + i]);
            }
            doNorm = (mx - mn) > 1.0f;
        }
        if (doNorm) {
            const float c1 = 1.0f - 1.0f / 255.0f;     // 254/255
            const float c2 = 1.0f + 10.0f / 255.0f;    // 265/255
            P1 = 255.0f * c1 * c2;                      // 263.9608
        }
    }

    // ---- stage B: vertical (height) resample -> s_ut[orow][icol] ----
    for (int t = tid; t < PAT_W * 8; t += 256) {
        int g  = t / PAT_W;
        int ic = t - g * PAT_W;
        int mb = g * 8;
        const float* p = &s_in[mb * PSTR + ic];
        float w0 = p[0 * PSTR], w1 = p[1 * PSTR], w2 = p[2 * PSTR];
        float w3 = p[3 * PSTR], w4 = p[4 * PSTR], w5 = p[5 * PSTR];
        float w6 = p[6 * PSTR], w7 = p[7 * PSTR], w8 = p[8 * PSTR];
        float* q = &s_ut[2 * mb * USTR + ic];
        #pragma unroll
        for (int mm = 0; mm < 8; mm++) {
            q[(2 * mm)     * USTR] = EVEN8(w0, w1, w2, w3, w4, w5, w6, w7);
            q[(2 * mm + 1) * USTR] = ODD8(w1, w2, w3, w4, w5, w6, w7, w8);
            w0 = w1; w1 = w2; w2 = w3; w3 = w4;
            w4 = w5; w5 = w6; w6 = w7; w7 = w8;
            if (mm < 7) w8 = p[(mm + 9) * PSTR];
        }
    }
    __syncthreads();

    // ---- stage C ----
    if (!WRITE) {
        const int orr = tid & (TILE_H - 1);
        const int h   = tid >> 7;
        const float* w = &s_ut[orr * USTR + 16 * h];

        float win[24];
        #pragma unroll
        for (int j = 0; j < 24; j++) win[j] = w[j];

        float vmin = __int_as_float(0x7f800000);
        float vmax = -vmin;
        #pragma unroll
        for (int n = 0; n < 16; n++) {
            float e = EVEN8(win[n],     win[n + 1], win[n + 2], win[n + 3],
                            win[n + 4], win[n + 5], win[n + 6], win[n + 7]);
            float o = ODD8 (win[n + 1], win[n + 2], win[n + 3], win[n + 4],
                            win[n + 5], win[n + 6], win[n + 7], win[n + 8]);
            vmin = fminf(vmin, fminf(e, o));
            vmax = fmaxf(vmax, fmaxf(e, o));
        }
        #pragma unroll
        for (int m = 16; m; m >>= 1) {
            vmin = fminf(vmin, __shfl_xor_sync(0xffffffffu, vmin, m));
            vmax = fmaxf(vmax, __shfl_xor_sync(0xffffffffu, vmax, m));
        }
        int w5 = tid >> 5, l = tid & 31;
        if (l == 0) { s_red[w5] = vmin; s_red[8 + w5] = vmax; }
        __syncthreads();
        if (tid == 0) {
            float a = s_red[0], b = s_red[8];
            #pragma unroll
            for (int i = 1; i < 8; i++) {
                a = fminf(a, s_red[i]);
                b = fmaxf(b, s_red[8 + i]);
            }
            int slot = blockIdx.y * 16 + blockIdx.x;
            g_pmin[bc * SLOTS + slot] = a;
            g_pmax[bc * SLOTS + slot] = b;
        }
    } else {
        const int seg  = tid & 15;
        const int rsub = tid >> 4;
        const int ic0  = 2 * seg;
        float* dstb = out + ((size_t)bc * OUT_SZ + blockIdx.y * TILE_H + rsub)
                          * OUT_SZ + blockIdx.x * TILE_W + seg * 4;
        #pragma unroll 2
        for (int it = 0; it < 8; it++) {
            const float* w = &s_ut[(it * 16 + rsub) * USTR + ic0];
            float w0 = w[0], w1 = w[1], w2 = w[2], w3 = w[3], w4 = w[4],
                  w5 = w[5], w6 = w[6], w7 = w[7], w8 = w[8], w9 = w[9];
            float p0 = EVEN8(w0, w1, w2, w3, w4, w5, w6, w7);
            float p1 = ODD8 (w1, w2, w3, w4, w5, w6, w7, w8);
            float p2 = EVEN8(w1, w2, w3, w4, w5, w6, w7, w8);
            float p3 = ODD8 (w2, w3, w4, w5, w6, w7, w8, w9);
            float f0 = (float)__float2uint_rz(fminf(p0 * P1, 255.0f));
            float f1 = (float)__float2uint_rz(fminf(p1 * P1, 255.0f));
            float f2 = (float)__float2uint_rz(fminf(p2 * P1, 255.0f));
            float f3 = (float)__float2uint_rz(fminf(p3 * P1, 255.0f));
            *reinterpret_cast<float4*>(dstb + (size_t)it * 16 * OUT_SZ) =
                make_float4(f0, f1, f2, f3);
        }
    }
}

extern "C" void kernel_launch(void* const* d_in, const int* in_sizes, int n_in,
                              void* d_out, int out_size)
{
    const float* x = (const float*)d_in[0];
    float* out = (float*)d_out;

    k_sample<<<NIMG, 256>>>(x);
    dim3 grid(OUT_SZ / TILE_W, OUT_SZ / TILE_H, NCH);
    k_resize<false><<<grid, 256>>>(x, nullptr);
    k_resize<true ><<<grid, 256>>>(x, out);
}